// round 1
// baseline (speedup 1.0000x reference)
#include <cuda_runtime.h>
#include <cuda_bf16.h>
#include <math.h>

// Problem constants
#define NN      256
#define NM      240      // |V_FROM| = rows 0..239
#define NT      240      // |V_TO|   = cols 16..255
#define ITERS   30
#define LRATE   0.1f
#define TOLV    1e-3f
#define ORDEPS  0.1f
// 4*NM = 960 ; NM*NN = 61440 ; 2*NM = 480

// ---------------- device scratch (no allocations allowed) ----------------
__device__ float g_At[NT * NM];     // At[k*240 + j] = A[j*256 + 16 + k]
__device__ float g_Gl[NM * NT];     // latent params
__device__ float g_mG[NM * NT];
__device__ float g_vG[NM * NT];
__device__ float g_Gmat[NM * NT];   // sigmoid(Gl) snapshot (pre-update)
__device__ float g_tau[NN];
__device__ float g_mT[NN];
__device__ float g_vT[NN];
__device__ float g_gradtau[NN];
__device__ float g_lodd_part[NM];
__device__ float g_lord_part[NN];
__device__ int      g_stop;
__device__ unsigned g_cnt;
__device__ unsigned g_cnt2;

// ---------------- helpers ----------------
__device__ __forceinline__ float sigmoidf_(float x) {
    return 1.0f / (1.0f + __expf(-x));
}

// Block-wide sum over 256 threads (callers pass 0 on inactive lanes).
// Deterministic (fixed tree). Result valid on thread 0.
__device__ __forceinline__ float blockReduce256(float v, float* red) {
    const unsigned m = 0xffffffffu;
    v += __shfl_down_sync(m, v, 16);
    v += __shfl_down_sync(m, v, 8);
    v += __shfl_down_sync(m, v, 4);
    v += __shfl_down_sync(m, v, 2);
    v += __shfl_down_sync(m, v, 1);
    int w = threadIdx.x >> 5;
    if ((threadIdx.x & 31) == 0) red[w] = v;
    __syncthreads();
    float r = 0.0f;
    if (threadIdx.x < 8) r = red[threadIdx.x];
    if (threadIdx.x < 32) {
        r += __shfl_down_sync(m, r, 4);
        r += __shfl_down_sync(m, r, 2);
        r += __shfl_down_sync(m, r, 1);
    }
    __syncthreads();
    return r;
}

// ---------------- init ----------------
__global__ void __launch_bounds__(256) k_init(const float* __restrict__ A,
                                              const float* __restrict__ Gl0,
                                              const float* __restrict__ tau0) {
    int idx = blockIdx.x * 256 + threadIdx.x;   // grid covers 61440
    if (idx < NM * NT) {
        g_Gl[idx] = Gl0[idx];
        g_mG[idx] = 0.0f;
        g_vG[idx] = 0.0f;
        int k = idx / NM;       // 0..239  (At row)
        int j = idx % NM;       // 0..239
        g_At[idx] = A[j * NN + 16 + k];
    }
    if (idx < NN) {
        g_tau[idx] = tau0[idx];
        g_mT[idx] = 0.0f;
        g_vT[idx] = 0.0f;
        g_gradtau[idx] = 0.0f;
        g_lord_part[idx] = 0.0f;
    }
    if (idx < NM) g_lodd_part[idx] = 0.0f;
    if (idx == 0) { g_stop = 0; g_cnt = 0u; g_cnt2 = 0u; }
}

// ---------------- per-iteration main: forward P + loss_odd + grad G + Adam(G) ----
// grid = 240 blocks (one per i-row), 256 threads
__global__ void __launch_bounds__(256) k_iter_main(const float* __restrict__ A,
                                                   float bc1inv, float bc2inv) {
    if (g_stop) return;
    const int i  = blockIdx.x;
    const int tx = threadIdx.x;

    __shared__ float Gs[NM];     // sigmoid
    __shared__ float Gn2[NM];    // -2*sigmoid
    __shared__ float Ds[NM];     // (P-T)*P/(2*NM)
    __shared__ float taus[NN];
    __shared__ float red[8];

    if (tx < NM) {
        float gl = g_Gl[i * NT + tx];
        float s  = sigmoidf_(gl);
        Gs[tx]  = s;
        Gn2[tx] = -2.0f * s;
        g_Gmat[i * NT + tx] = s;          // snapshot BEFORE update (for tau pass)
    }
    taus[tx] = g_tau[tx];
    __syncthreads();

    // ---- forward: thread = j ----
    float lossp = 0.0f;
    if (tx < NM) {
        const int j = tx;
        float p0 = 1.0f, p1 = 1.0f, p2 = 1.0f, p3 = 1.0f;
        #pragma unroll 4
        for (int k = 0; k < NT; k += 4) {
            p0 *= fmaf(g_At[(k + 0) * NM + j], Gn2[k + 0], 1.0f);
            p1 *= fmaf(g_At[(k + 1) * NM + j], Gn2[k + 1], 1.0f);
            p2 *= fmaf(g_At[(k + 2) * NM + j], Gn2[k + 2], 1.0f);
            p3 *= fmaf(g_At[(k + 3) * NM + j], Gn2[k + 3], 1.0f);
        }
        float P = (p0 * p1) * (p2 * p3);
        float T = (j == i) ? -1.0f : 1.0f;
        float e = P - T;
        lossp = e * e;
        Ds[j] = e * P * (1.0f / 480.0f);   // 2(P-T)/(4NM) * P
    }
    __syncthreads();   // Ds visible to all

    float blocksum = blockReduce256(lossp, red);
    if (tx == 0) g_lodd_part[i] = blocksum;

    // ---- backward: thread = k ----
    if (tx < NM) {
        const int k   = tx;
        const float gn2 = Gn2[k];
        const float gv  = Gs[k];
        const float* Acol = A + 16 + k;    // A[j*256 + 16 + k], coalesced over k
        float s0 = 0.0f, s1 = 0.0f;
        #pragma unroll 2
        for (int j = 0; j < NM; j += 2) {
            float a0 = Acol[(j + 0) * NN];
            float a1 = Acol[(j + 1) * NN];
            float t0 = fmaf(a0, gn2, 1.0f);
            float t1 = fmaf(a1, gn2, 1.0f);
            float q0 = __fdividef(Ds[j + 0] * a0, t0);
            float q1 = __fdividef(Ds[j + 1] * a1, t1);
            s0 += (t0 != 0.0f) ? q0 : 0.0f;   // exact-zero term -> LOO prod underflows -> 0
            s1 += (t1 != 0.0f) ? q1 : 0.0f;
        }
        float gradOdd = -2.0f * (s0 + s1);

        float d = taus[i] - taus[16 + k] + ORDEPS;
        float r = fmaxf(d, 0.0f);
        float gradOrd = r * r * (1.0f / 61440.0f);

        float grad = (gradOdd + gradOrd) * (gv * (1.0f - gv));   // sigmoid chain

        int idx = i * NT + k;
        float m = 0.9f   * g_mG[idx] + 0.1f   * grad;
        float v = 0.999f * g_vG[idx] + 0.001f * grad * grad;
        g_mG[idx] = m;
        g_vG[idx] = v;
        float upd = LRATE * (m * bc1inv) / (sqrtf(v * bc2inv) + 1e-8f);
        g_Gl[idx] -= upd;
    }
}

// ---------------- per-iteration tau: grad tau + loss_order + Adam(tau) + stop ----
// grid = 256 blocks (one per tau index m), 256 threads; last block finalizes
__global__ void __launch_bounds__(256) k_iter_tau(float bc1inv, float bc2inv) {
    if (g_stop) return;
    const int m  = blockIdx.x;     // 0..255
    const int tx = threadIdx.x;
    __shared__ float red[8];
    __shared__ unsigned isLast;

    float taum = g_tau[m];

    float s1 = 0.0f, sl = 0.0f, s2 = 0.0f;
    if (tx < NM) {
        if (m < NM) {
            float d = taum - g_tau[16 + tx] + ORDEPS;
            float r = fmaxf(d, 0.0f);
            float gv = g_Gmat[m * NT + tx];
            s1 = gv * r;
            sl = gv * r * r;
        }
        if (m >= 16) {
            float d = g_tau[tx] - taum + ORDEPS;
            float r = fmaxf(d, 0.0f);
            s2 = g_Gmat[tx * NT + (m - 16)] * r;
        }
    }
    float S1 = blockReduce256(s1, red);
    float SL = blockReduce256(sl, red);
    float S2 = blockReduce256(s2, red);

    if (tx == 0) {
        g_gradtau[m]   = (2.0f / 61440.0f) * (S1 - S2);
        g_lord_part[m] = SL;                 // 0 for m >= 240
        __threadfence();
        unsigned c = atomicAdd(&g_cnt, 1u);
        isLast = (c == (unsigned)(gridDim.x - 1)) ? 1u : 0u;
    }
    __syncthreads();

    if (isLast) {
        // Adam for tau (256 params, one per thread)
        float gt = ((volatile float*)g_gradtau)[tx];
        float mm = 0.9f   * g_mT[tx] + 0.1f   * gt;
        float vv = 0.999f * g_vT[tx] + 0.001f * gt * gt;
        g_mT[tx] = mm;
        g_vT[tx] = vv;
        g_tau[tx] -= LRATE * (mm * bc1inv) / (sqrtf(vv * bc2inv) + 1e-8f);

        // deterministic loss combine + stop flag
        __shared__ float sm[256];
        float lo = (tx < NM) ? ((volatile float*)g_lodd_part)[tx] : 0.0f;
        sm[tx] = lo;
        __syncthreads();
        for (int st = 128; st > 0; st >>= 1) {
            if (tx < st) sm[tx] += sm[tx + st];
            __syncthreads();
        }
        float lossodd = sm[0];
        __syncthreads();
        float lrp = ((volatile float*)g_lord_part)[tx];
        sm[tx] = lrp;
        __syncthreads();
        for (int st = 128; st > 0; st >>= 1) {
            if (tx < st) sm[tx] += sm[tx + st];
            __syncthreads();
        }
        if (tx == 0) {
            float loss = lossodd * (1.0f / 960.0f) + sm[0] * (1.0f / 61440.0f);
            if (loss < TOLV) g_stop = 1;
            g_cnt = 0u;
        }
    }
}

// ---------------- epilogue 1: forward at final params (loss_odd parts) --------
__global__ void __launch_bounds__(256) k_final_odd() {
    const int i  = blockIdx.x;
    const int tx = threadIdx.x;
    __shared__ float Gn2[NM];
    __shared__ float red[8];

    if (tx < NM) {
        float s = sigmoidf_(g_Gl[i * NT + tx]);
        Gn2[tx] = -2.0f * s;
        g_Gmat[i * NT + tx] = s;     // final G for epilogue 2
    }
    __syncthreads();

    float lossp = 0.0f;
    if (tx < NM) {
        const int j = tx;
        float p0 = 1.0f, p1 = 1.0f, p2 = 1.0f, p3 = 1.0f;
        #pragma unroll 4
        for (int k = 0; k < NT; k += 4) {
            p0 *= fmaf(g_At[(k + 0) * NM + j], Gn2[k + 0], 1.0f);
            p1 *= fmaf(g_At[(k + 1) * NM + j], Gn2[k + 1], 1.0f);
            p2 *= fmaf(g_At[(k + 2) * NM + j], Gn2[k + 2], 1.0f);
            p3 *= fmaf(g_At[(k + 3) * NM + j], Gn2[k + 3], 1.0f);
        }
        float P = (p0 * p1) * (p2 * p3);
        float T = (j == i) ? -1.0f : 1.0f;
        float e = P - T;
        lossp = e * e;
    }
    float blocksum = blockReduce256(lossp, red);
    if (tx == 0) g_lodd_part[i] = blocksum;
}

// ---------------- epilogue 2: loss_order at final params + output -------------
// grid = 240 blocks, last block writes out[0]
__global__ void __launch_bounds__(256) k_final_out(float* __restrict__ out) {
    const int m  = blockIdx.x;   // 0..239
    const int tx = threadIdx.x;
    __shared__ float red[8];
    __shared__ unsigned isLast;

    float sl = 0.0f;
    if (tx < NM) {
        float d = g_tau[m] - g_tau[16 + tx] + ORDEPS;
        float r = fmaxf(d, 0.0f);
        sl = g_Gmat[m * NT + tx] * r * r;
    }
    float SL = blockReduce256(sl, red);
    if (tx == 0) {
        g_lord_part[m] = SL;
        __threadfence();
        unsigned c = atomicAdd(&g_cnt2, 1u);
        isLast = (c == (unsigned)(gridDim.x - 1)) ? 1u : 0u;
    }
    __syncthreads();

    if (isLast) {
        __shared__ float sm[256];
        float lo = (tx < NM) ? ((volatile float*)g_lodd_part)[tx] : 0.0f;
        sm[tx] = lo;
        __syncthreads();
        for (int st = 128; st > 0; st >>= 1) {
            if (tx < st) sm[tx] += sm[tx + st];
            __syncthreads();
        }
        float lossodd = sm[0];
        __syncthreads();
        float lrp = (tx < NM) ? ((volatile float*)g_lord_part)[tx] : 0.0f;
        sm[tx] = lrp;
        __syncthreads();
        for (int st = 128; st > 0; st >>= 1) {
            if (tx < st) sm[tx] += sm[tx + st];
            __syncthreads();
        }
        if (tx == 0) {
            out[0] = lossodd * (1.0f / 960.0f) + sm[0] * (1.0f / 61440.0f);
            g_cnt2 = 0u;
        }
    }
}

// ---------------- launch ----------------
extern "C" void kernel_launch(void* const* d_in, const int* in_sizes, int n_in,
                              void* d_out, int out_size) {
    const float* A    = (const float*)d_in[0];   // (256,256)
    const float* Gl0  = (const float*)d_in[1];   // (240,240)
    const float* tau0 = (const float*)d_in[2];   // (256,)
    float* out = (float*)d_out;

    k_init<<<240, 256>>>(A, Gl0, tau0);

    double b1t = 1.0, b2t = 1.0;
    for (int t = 1; t <= ITERS; ++t) {
        b1t *= 0.9;
        b2t *= 0.999;
        float bc1inv = (float)(1.0 / (1.0 - b1t));
        float bc2inv = (float)(1.0 / (1.0 - b2t));
        k_iter_main<<<240, 256>>>(A, bc1inv, bc2inv);
        k_iter_tau<<<256, 256>>>(bc1inv, bc2inv);
    }

    k_final_odd<<<240, 256>>>();
    k_final_out<<<240, 256>>>(out);
}

// round 2
// speedup vs baseline: 1.0001x; 1.0001x over previous
#include <cuda_runtime.h>
#include <cuda_bf16.h>
#include <math.h>

// Problem constants
#define NN      256
#define NM      240      // |V_FROM| = rows 0..239
#define NT      240      // |V_TO|   = cols 16..255
#define ITERS   30
#define LRATE   0.1f
#define TOLV    1e-3f
#define ORDEPS  0.1f
// 4*NM = 960 ; NM*NN = 61440 ; 2*NM = 480

// ---------------- device scratch (no allocations allowed) ----------------
__device__ float g_At[NT * NM];     // At[k*240 + j] = A[j*256 + 16 + k]
__device__ float g_Gl[NM * NT];     // latent params
__device__ float g_mG[NM * NT];
__device__ float g_vG[NM * NT];
__device__ float g_Gmat[NM * NT];   // sigmoid(Gl) snapshot (pre-update)
__device__ float g_tau[NN];
__device__ float g_mT[NN];
__device__ float g_vT[NN];
__device__ float g_gradtau[NN];
__device__ float g_lodd_part[NM];
__device__ float g_lord_part[NN];
__device__ int      g_stop;
__device__ unsigned g_cnt;
__device__ unsigned g_cnt2;

// ---------------- helpers ----------------
__device__ __forceinline__ float sigmoidf_(float x) {
    return 1.0f / (1.0f + __expf(-x));
}

// Block-wide sum over 256 threads (callers pass 0 on inactive lanes).
// Deterministic (fixed tree). Result valid on thread 0.
__device__ __forceinline__ float blockReduce256(float v, float* red) {
    const unsigned m = 0xffffffffu;
    v += __shfl_down_sync(m, v, 16);
    v += __shfl_down_sync(m, v, 8);
    v += __shfl_down_sync(m, v, 4);
    v += __shfl_down_sync(m, v, 2);
    v += __shfl_down_sync(m, v, 1);
    int w = threadIdx.x >> 5;
    if ((threadIdx.x & 31) == 0) red[w] = v;
    __syncthreads();
    float r = 0.0f;
    if (threadIdx.x < 8) r = red[threadIdx.x];
    if (threadIdx.x < 32) {
        r += __shfl_down_sync(m, r, 4);
        r += __shfl_down_sync(m, r, 2);
        r += __shfl_down_sync(m, r, 1);
    }
    __syncthreads();
    return r;
}

// ---------------- init ----------------
__global__ void __launch_bounds__(256) k_init(const float* __restrict__ A,
                                              const float* __restrict__ Gl0,
                                              const float* __restrict__ tau0) {
    int idx = blockIdx.x * 256 + threadIdx.x;   // grid covers 61440
    if (idx < NM * NT) {
        g_Gl[idx] = Gl0[idx];
        g_mG[idx] = 0.0f;
        g_vG[idx] = 0.0f;
        int k = idx / NM;       // 0..239  (At row)
        int j = idx % NM;       // 0..239
        g_At[idx] = A[j * NN + 16 + k];
    }
    if (idx < NN) {
        g_tau[idx] = tau0[idx];
        g_mT[idx] = 0.0f;
        g_vT[idx] = 0.0f;
        g_gradtau[idx] = 0.0f;
        g_lord_part[idx] = 0.0f;
    }
    if (idx < NM) g_lodd_part[idx] = 0.0f;
    if (idx == 0) { g_stop = 0; g_cnt = 0u; g_cnt2 = 0u; }
}

// ---------------- per-iteration main: forward P + loss_odd + grad G + Adam(G) ----
// grid = 240 blocks (one per i-row), 256 threads
__global__ void __launch_bounds__(256) k_iter_main(const float* __restrict__ A,
                                                   float bc1inv, float bc2inv) {
    if (g_stop) return;
    const int i  = blockIdx.x;
    const int tx = threadIdx.x;

    __shared__ float Gs[NM];     // sigmoid
    __shared__ float Gn2[NM];    // -2*sigmoid
    __shared__ float Ds[NM];     // (P-T)*P/(2*NM)
    __shared__ float taus[NN];
    __shared__ float red[8];

    if (tx < NM) {
        float gl = g_Gl[i * NT + tx];
        float s  = sigmoidf_(gl);
        Gs[tx]  = s;
        Gn2[tx] = -2.0f * s;
        g_Gmat[i * NT + tx] = s;          // snapshot BEFORE update (for tau pass)
    }
    taus[tx] = g_tau[tx];
    __syncthreads();

    // ---- forward: thread = j ----
    float lossp = 0.0f;
    if (tx < NM) {
        const int j = tx;
        float p0 = 1.0f, p1 = 1.0f, p2 = 1.0f, p3 = 1.0f;
        #pragma unroll 4
        for (int k = 0; k < NT; k += 4) {
            p0 *= fmaf(g_At[(k + 0) * NM + j], Gn2[k + 0], 1.0f);
            p1 *= fmaf(g_At[(k + 1) * NM + j], Gn2[k + 1], 1.0f);
            p2 *= fmaf(g_At[(k + 2) * NM + j], Gn2[k + 2], 1.0f);
            p3 *= fmaf(g_At[(k + 3) * NM + j], Gn2[k + 3], 1.0f);
        }
        float P = (p0 * p1) * (p2 * p3);
        float T = (j == i) ? -1.0f : 1.0f;
        float e = P - T;
        lossp = e * e;
        Ds[j] = e * P * (1.0f / 480.0f);   // 2(P-T)/(4NM) * P
    }
    __syncthreads();   // Ds visible to all

    float blocksum = blockReduce256(lossp, red);
    if (tx == 0) g_lodd_part[i] = blocksum;

    // ---- backward: thread = k ----
    if (tx < NM) {
        const int k   = tx;
        const float gn2 = Gn2[k];
        const float gv  = Gs[k];
        const float* Acol = A + 16 + k;    // A[j*256 + 16 + k], coalesced over k
        float s0 = 0.0f, s1 = 0.0f;
        #pragma unroll 2
        for (int j = 0; j < NM; j += 2) {
            float a0 = Acol[(j + 0) * NN];
            float a1 = Acol[(j + 1) * NN];
            float t0 = fmaf(a0, gn2, 1.0f);
            float t1 = fmaf(a1, gn2, 1.0f);
            float q0 = __fdividef(Ds[j + 0] * a0, t0);
            float q1 = __fdividef(Ds[j + 1] * a1, t1);
            s0 += (t0 != 0.0f) ? q0 : 0.0f;   // exact-zero term -> LOO prod underflows -> 0
            s1 += (t1 != 0.0f) ? q1 : 0.0f;
        }
        float gradOdd = -2.0f * (s0 + s1);

        float d = taus[i] - taus[16 + k] + ORDEPS;
        float r = fmaxf(d, 0.0f);
        float gradOrd = r * r * (1.0f / 61440.0f);

        float grad = (gradOdd + gradOrd) * (gv * (1.0f - gv));   // sigmoid chain

        int idx = i * NT + k;
        float m = 0.9f   * g_mG[idx] + 0.1f   * grad;
        float v = 0.999f * g_vG[idx] + 0.001f * grad * grad;
        g_mG[idx] = m;
        g_vG[idx] = v;
        float upd = LRATE * (m * bc1inv) / (sqrtf(v * bc2inv) + 1e-8f);
        g_Gl[idx] -= upd;
    }
}

// ---------------- per-iteration tau: grad tau + loss_order + Adam(tau) + stop ----
// grid = 256 blocks (one per tau index m), 256 threads; last block finalizes
__global__ void __launch_bounds__(256) k_iter_tau(float bc1inv, float bc2inv) {
    if (g_stop) return;
    const int m  = blockIdx.x;     // 0..255
    const int tx = threadIdx.x;
    __shared__ float red[8];
    __shared__ unsigned isLast;

    float taum = g_tau[m];

    float s1 = 0.0f, sl = 0.0f, s2 = 0.0f;
    if (tx < NM) {
        if (m < NM) {
            float d = taum - g_tau[16 + tx] + ORDEPS;
            float r = fmaxf(d, 0.0f);
            float gv = g_Gmat[m * NT + tx];
            s1 = gv * r;
            sl = gv * r * r;
        }
        if (m >= 16) {
            float d = g_tau[tx] - taum + ORDEPS;
            float r = fmaxf(d, 0.0f);
            s2 = g_Gmat[tx * NT + (m - 16)] * r;
        }
    }
    float S1 = blockReduce256(s1, red);
    float SL = blockReduce256(sl, red);
    float S2 = blockReduce256(s2, red);

    if (tx == 0) {
        g_gradtau[m]   = (2.0f / 61440.0f) * (S1 - S2);
        g_lord_part[m] = SL;                 // 0 for m >= 240
        __threadfence();
        unsigned c = atomicAdd(&g_cnt, 1u);
        isLast = (c == (unsigned)(gridDim.x - 1)) ? 1u : 0u;
    }
    __syncthreads();

    if (isLast) {
        // Adam for tau (256 params, one per thread)
        float gt = ((volatile float*)g_gradtau)[tx];
        float mm = 0.9f   * g_mT[tx] + 0.1f   * gt;
        float vv = 0.999f * g_vT[tx] + 0.001f * gt * gt;
        g_mT[tx] = mm;
        g_vT[tx] = vv;
        g_tau[tx] -= LRATE * (mm * bc1inv) / (sqrtf(vv * bc2inv) + 1e-8f);

        // deterministic loss combine + stop flag
        __shared__ float sm[256];
        float lo = (tx < NM) ? ((volatile float*)g_lodd_part)[tx] : 0.0f;
        sm[tx] = lo;
        __syncthreads();
        for (int st = 128; st > 0; st >>= 1) {
            if (tx < st) sm[tx] += sm[tx + st];
            __syncthreads();
        }
        float lossodd = sm[0];
        __syncthreads();
        float lrp = ((volatile float*)g_lord_part)[tx];
        sm[tx] = lrp;
        __syncthreads();
        for (int st = 128; st > 0; st >>= 1) {
            if (tx < st) sm[tx] += sm[tx + st];
            __syncthreads();
        }
        if (tx == 0) {
            float loss = lossodd * (1.0f / 960.0f) + sm[0] * (1.0f / 61440.0f);
            if (loss < TOLV) g_stop = 1;
            g_cnt = 0u;
        }
    }
}

// ---------------- epilogue 1: forward at final params (loss_odd parts) --------
__global__ void __launch_bounds__(256) k_final_odd() {
    const int i  = blockIdx.x;
    const int tx = threadIdx.x;
    __shared__ float Gn2[NM];
    __shared__ float red[8];

    if (tx < NM) {
        float s = sigmoidf_(g_Gl[i * NT + tx]);
        Gn2[tx] = -2.0f * s;
        g_Gmat[i * NT + tx] = s;     // final G for epilogue 2
    }
    __syncthreads();

    float lossp = 0.0f;
    if (tx < NM) {
        const int j = tx;
        float p0 = 1.0f, p1 = 1.0f, p2 = 1.0f, p3 = 1.0f;
        #pragma unroll 4
        for (int k = 0; k < NT; k += 4) {
            p0 *= fmaf(g_At[(k + 0) * NM + j], Gn2[k + 0], 1.0f);
            p1 *= fmaf(g_At[(k + 1) * NM + j], Gn2[k + 1], 1.0f);
            p2 *= fmaf(g_At[(k + 2) * NM + j], Gn2[k + 2], 1.0f);
            p3 *= fmaf(g_At[(k + 3) * NM + j], Gn2[k + 3], 1.0f);
        }
        float P = (p0 * p1) * (p2 * p3);
        float T = (j == i) ? -1.0f : 1.0f;
        float e = P - T;
        lossp = e * e;
    }
    float blocksum = blockReduce256(lossp, red);
    if (tx == 0) g_lodd_part[i] = blocksum;
}

// ---------------- epilogue 2: loss_order at final params + output -------------
// grid = 240 blocks, last block writes out[0]
__global__ void __launch_bounds__(256) k_final_out(float* __restrict__ out) {
    const int m  = blockIdx.x;   // 0..239
    const int tx = threadIdx.x;
    __shared__ float red[8];
    __shared__ unsigned isLast;

    float sl = 0.0f;
    if (tx < NM) {
        float d = g_tau[m] - g_tau[16 + tx] + ORDEPS;
        float r = fmaxf(d, 0.0f);
        sl = g_Gmat[m * NT + tx] * r * r;
    }
    float SL = blockReduce256(sl, red);
    if (tx == 0) {
        g_lord_part[m] = SL;
        __threadfence();
        unsigned c = atomicAdd(&g_cnt2, 1u);
        isLast = (c == (unsigned)(gridDim.x - 1)) ? 1u : 0u;
    }
    __syncthreads();

    if (isLast) {
        __shared__ float sm[256];
        float lo = (tx < NM) ? ((volatile float*)g_lodd_part)[tx] : 0.0f;
        sm[tx] = lo;
        __syncthreads();
        for (int st = 128; st > 0; st >>= 1) {
            if (tx < st) sm[tx] += sm[tx + st];
            __syncthreads();
        }
        float lossodd = sm[0];
        __syncthreads();
        float lrp = (tx < NM) ? ((volatile float*)g_lord_part)[tx] : 0.0f;
        sm[tx] = lrp;
        __syncthreads();
        for (int st = 128; st > 0; st >>= 1) {
            if (tx < st) sm[tx] += sm[tx + st];
            __syncthreads();
        }
        if (tx == 0) {
            out[0] = lossodd * (1.0f / 960.0f) + sm[0] * (1.0f / 61440.0f);
            g_cnt2 = 0u;
        }
    }
}

// ---------------- launch ----------------
extern "C" void kernel_launch(void* const* d_in, const int* in_sizes, int n_in,
                              void* d_out, int out_size) {
    const float* A    = (const float*)d_in[0];   // (256,256)
    const float* Gl0  = (const float*)d_in[1];   // (240,240)
    const float* tau0 = (const float*)d_in[2];   // (256,)
    float* out = (float*)d_out;

    k_init<<<240, 256>>>(A, Gl0, tau0);

    double b1t = 1.0, b2t = 1.0;
    for (int t = 1; t <= ITERS; ++t) {
        b1t *= 0.9;
        b2t *= 0.999;
        float bc1inv = (float)(1.0 / (1.0 - b1t));
        float bc2inv = (float)(1.0 / (1.0 - b2t));
        k_iter_main<<<240, 256>>>(A, bc1inv, bc2inv);
        k_iter_tau<<<256, 256>>>(bc1inv, bc2inv);
    }

    k_final_odd<<<240, 256>>>();
    k_final_out<<<240, 256>>>(out);
}